// round 5
// baseline (speedup 1.0000x reference)
#include <cuda_runtime.h>
#include <cstdint>

#define INV_SQRT2 0.7071067811865476f

// x: (B=64, S=4096, F=256) fp32 contiguous -> out (B, 2048, 512):
//   out[b,s2,2f]   = (x[b,2s2,f] + x[b,2s2+1,f]) * INV_SQRT2
//   out[b,s2,2f+1] = (x[b,2s2,f] - x[b,2s2+1,f]) * INV_SQRT2
//
// 256-bit granularity version (sm_100+ LDG.E.256 / STG.E.256):
//   32 threads per pair p. Thread j loads 8 consecutive floats of x0 and of
//   x1 (one v8 load each, full 32B sector per lane), emits 16 consecutive
//   output floats as two v8 stores. Warp traffic: 2x 1KB contiguous loads,
//   2KB contiguous store. Streaming (.cs) qualifiers throughout.

__device__ __forceinline__ void ldg256_cs(const float* p, float* v) {
    asm volatile(
        "ld.global.cs.v8.f32 {%0,%1,%2,%3,%4,%5,%6,%7}, [%8];"
        : "=f"(v[0]), "=f"(v[1]), "=f"(v[2]), "=f"(v[3]),
          "=f"(v[4]), "=f"(v[5]), "=f"(v[6]), "=f"(v[7])
        : "l"(p));
}

__device__ __forceinline__ void stg256_cs(float* p, const float* v) {
    asm volatile(
        "st.global.cs.v8.f32 [%0], {%1,%2,%3,%4,%5,%6,%7,%8};"
        :: "l"(p),
           "f"(v[0]), "f"(v[1]), "f"(v[2]), "f"(v[3]),
           "f"(v[4]), "f"(v[5]), "f"(v[6]), "f"(v[7])
        : "memory");
}

__global__ void __launch_bounds__(256) haar_kernel(const float* __restrict__ x,
                                                   float* __restrict__ out,
                                                   int total_threads)
{
    int tid = blockIdx.x * blockDim.x + threadIdx.x;
    if (tid >= total_threads) return;

    int p = tid >> 5;        // pair index (b*S/2 + s2)
    int j = tid & 31;        // 8-float chunk within the F=256 row

    const float* x0 = x + (size_t)p * 512 + 8 * j;   // row 2s2
    const float* x1 = x0 + 256;                       // row 2s2+1

    float a[8], b[8];
    ldg256_cs(x0, a);
    ldg256_cs(x1, b);

    float o[16];
    #pragma unroll
    for (int k = 0; k < 8; k++) {
        o[2 * k]     = (a[k] + b[k]) * INV_SQRT2;
        o[2 * k + 1] = (a[k] - b[k]) * INV_SQRT2;
    }

    float* op = out + (size_t)p * 512 + 16 * j;
    stg256_cs(op,     o);
    stg256_cs(op + 8, o + 8);
}

extern "C" void kernel_launch(void* const* d_in, const int* in_sizes, int n_in,
                              void* d_out, int out_size)
{
    const float* x = (const float*)d_in[0];
    float* out = (float*)d_out;

    // 16 input floats consumed per thread.
    int total_threads = in_sizes[0] / 16;

    int threads = 256;
    int blocks = (total_threads + threads - 1) / threads;
    haar_kernel<<<blocks, threads>>>(x, out, total_threads);
}